// round 1
// baseline (speedup 1.0000x reference)
#include <cuda_runtime.h>

#define ELEMF 64
#define NBRF  32
#define KTOT  160
#define COUT  128
#define EPS   1e-5f
#define E_MAX 1600000
#define N_MAX 50000

// Scratch (device globals; no allocations allowed)
__device__ float g_hidden[(size_t)E_MAX * COUT];   // pre-BN1 hidden (E,128)
__device__ float g_sums[(size_t)N_MAX * ELEMF];    // segment sums (N,64)
__device__ float g_stats1[2 * COUT];               // sum / sumsq per hidden col
__device__ float g_stats2[2 * ELEMF];              // sum / sumsq per summed col

__global__ void zero_kernel(int n_sums) {
    int i = blockIdx.x * blockDim.x + threadIdx.x;
    int stride = gridDim.x * blockDim.x;
    for (int j = i; j < n_sums; j += stride) g_sums[j] = 0.f;
    if (i < 2 * COUT)  g_stats1[i] = 0.f;
    if (i < 2 * ELEMF) g_stats2[i] = 0.f;
}

// Fused gather + GEMM: hidden[e] = concat(atom[self], atom[nbr], nbr_fea[e]) @ W + b
// Tile: 64 edges x 128 cols, BK=32 (chunk boundaries align with the 64/64/32 concat).
// Also accumulates per-column sum / sumsq for BN1 into g_stats1.
__global__ __launch_bounds__(256) void gemm_stats_kernel(
    const float* __restrict__ atom, const float* __restrict__ nbrfea,
    const int* __restrict__ selfIdx, const int* __restrict__ nbrIdx,
    const float* __restrict__ W, const float* __restrict__ bias, int E)
{
    __shared__ float sA[64][33];
    __shared__ float sW[32][128];
    __shared__ int   sSelf[64];
    __shared__ int   sNbr[64];
    __shared__ float redS[8][128];
    __shared__ float redQ[8][128];

    const int tid  = threadIdx.x;
    const int tcol = tid & 31;   // 32 col groups of 4
    const int trow = tid >> 5;   // 8 row groups of 8
    const int e0   = blockIdx.x * 64;

    if (tid < 64) {
        int e = e0 + tid;
        sSelf[tid] = (e < E) ? selfIdx[e] : 0;
    } else if (tid < 128) {
        int e = e0 + (tid - 64);
        sNbr[tid - 64] = (e < E) ? nbrIdx[e] : 0;
    }
    __syncthreads();

    float acc[8][4];
#pragma unroll
    for (int i = 0; i < 8; ++i)
#pragma unroll
        for (int j = 0; j < 4; ++j) acc[i][j] = 0.f;

#pragma unroll
    for (int chunk = 0; chunk < 5; ++chunk) {
        const int k0 = chunk * 32;
        // W tile: 32x128 = 4096 elems, 16 per thread, coalesced
#pragma unroll
        for (int i = 0; i < 16; ++i) {
            int idx = i * 256 + tid;
            sW[idx >> 7][idx & 127] = W[(k0 + (idx >> 7)) * COUT + (idx & 127)];
        }
        // A tile (gathered): 64x32 = 2048 elems, 8 per thread
#pragma unroll
        for (int i = 0; i < 8; ++i) {
            int idx = i * 256 + tid;
            int r = idx >> 5, c = idx & 31;
            float v = 0.f;
            if (e0 + r < E) {
                if (chunk < 2)      v = atom[sSelf[r] * ELEMF + k0 + c];
                else if (chunk < 4) v = atom[sNbr[r]  * ELEMF + (k0 - 64) + c];
                else                v = nbrfea[(size_t)(e0 + r) * NBRF + c];
            }
            sA[r][c] = v;
        }
        __syncthreads();
#pragma unroll
        for (int kk = 0; kk < 32; ++kk) {
            float a[8];
#pragma unroll
            for (int i = 0; i < 8; ++i) a[i] = sA[trow * 8 + i][kk];
            float4 wv = *reinterpret_cast<const float4*>(&sW[kk][tcol * 4]);
            float w0 = wv.x, w1 = wv.y, w2 = wv.z, w3 = wv.w;
#pragma unroll
            for (int i = 0; i < 8; ++i) {
                acc[i][0] = fmaf(a[i], w0, acc[i][0]);
                acc[i][1] = fmaf(a[i], w1, acc[i][1]);
                acc[i][2] = fmaf(a[i], w2, acc[i][2]);
                acc[i][3] = fmaf(a[i], w3, acc[i][3]);
            }
        }
        __syncthreads();
    }

    // bias, store, per-thread column stats
    float4 bv = *reinterpret_cast<const float4*>(&bias[tcol * 4]);
    float bb[4] = {bv.x, bv.y, bv.z, bv.w};
    float csum[4] = {0.f, 0.f, 0.f, 0.f};
    float csq[4]  = {0.f, 0.f, 0.f, 0.f};
#pragma unroll
    for (int i = 0; i < 8; ++i) {
        int e = e0 + trow * 8 + i;
        if (e < E) {
            float v[4];
#pragma unroll
            for (int j = 0; j < 4; ++j) {
                v[j] = acc[i][j] + bb[j];
                csum[j] += v[j];
                csq[j]  += v[j] * v[j];
            }
            float4 o = make_float4(v[0], v[1], v[2], v[3]);
            *reinterpret_cast<float4*>(&g_hidden[(size_t)e * COUT + tcol * 4]) = o;
        }
    }
#pragma unroll
    for (int j = 0; j < 4; ++j) {
        redS[trow][tcol * 4 + j] = csum[j];
        redQ[trow][tcol * 4 + j] = csq[j];
    }
    __syncthreads();
    if (tid < 128) {
        float s = 0.f, q = 0.f;
#pragma unroll
        for (int r = 0; r < 8; ++r) { s += redS[r][tid]; q += redQ[r][tid]; }
        atomicAdd(&g_stats1[tid], s);
        atomicAdd(&g_stats1[COUT + tid], q);
    }
}

__device__ __forceinline__ float softplusf(float x) {
    return (x > 15.f) ? x : log1pf(expf(x));
}

// Apply BN1, sigmoid(filter)*softplus(core), segment-sum over sorted self idx.
// Layout: c = tid&63 (feature), lane = tid>>6; each lane walks 64 contiguous edges
// accumulating in a register, flushing via atomicAdd on atom-id change.
__global__ __launch_bounds__(256) void msg_segsum_kernel(
    const int* __restrict__ selfIdx,
    const float* __restrict__ gamma1, const float* __restrict__ beta1,
    int E, float invE)
{
    __shared__ float s1[128], t1[128];
    const int tid = threadIdx.x;
    if (tid < 128) {
        float mean = g_stats1[tid] * invE;
        float var  = g_stats1[128 + tid] * invE - mean * mean;
        float r = rsqrtf(var + EPS);
        float g = gamma1[tid];
        s1[tid] = g * r;
        t1[tid] = beta1[tid] - g * mean * r;
    }
    __syncthreads();

    const int c = tid & 63;
    const int lane = tid >> 6;
    const int CHUNK = 64;
    long gl = (long)blockIdx.x * 4 + lane;
    int es = (int)(gl * CHUNK);
    if (es >= E) return;
    int ee = min(es + CHUNK, E);

    const float sf = s1[c],      tf = t1[c];
    const float sc = s1[64 + c], tc = t1[64 + c];

    int cur = selfIdx[es];
    float accv = 0.f;
    for (int e = es; e < ee; ++e) {
        int a = selfIdx[e];                  // warp-uniform (same e across warp)
        if (a != cur) {
            atomicAdd(&g_sums[(size_t)cur * ELEMF + c], accv);
            cur = a; accv = 0.f;
        }
        float f = fmaf(sf, g_hidden[(size_t)e * COUT + c], tf);
        float g = fmaf(sc, g_hidden[(size_t)e * COUT + 64 + c], tc);
        float sig = 1.f / (1.f + expf(-f));
        accv = fmaf(sig, softplusf(g), accv);
    }
    atomicAdd(&g_sums[(size_t)cur * ELEMF + c], accv);
}

// Column stats over g_sums (N,64) for BN2
__global__ __launch_bounds__(256) void stats2_kernel(int Nn) {
    __shared__ float rs[4][64];
    __shared__ float rq[4][64];
    const int tid = threadIdx.x;
    const int c = tid & 63, rl = tid >> 6;
    float s = 0.f, q = 0.f;
    for (int row = blockIdx.x * 4 + rl; row < Nn; row += gridDim.x * 4) {
        float v = g_sums[(size_t)row * ELEMF + c];
        s += v; q += v * v;
    }
    rs[rl][c] = s; rq[rl][c] = q;
    __syncthreads();
    if (tid < 64) {
        float ss = 0.f, qq = 0.f;
#pragma unroll
        for (int r = 0; r < 4; ++r) { ss += rs[r][tid]; qq += rq[r][tid]; }
        atomicAdd(&g_stats2[tid], ss);
        atomicAdd(&g_stats2[64 + tid], qq);
    }
}

// BN2 + residual + softplus -> out (N,64)
__global__ __launch_bounds__(256) void out_kernel(
    const float* __restrict__ atom,
    const float* __restrict__ gamma2, const float* __restrict__ beta2,
    float* __restrict__ outp, int Nn, float invN)
{
    __shared__ float s2[64], t2[64];
    const int tid = threadIdx.x;
    if (tid < 64) {
        float mean = g_stats2[tid] * invN;
        float var  = g_stats2[64 + tid] * invN - mean * mean;
        float r = rsqrtf(var + EPS);
        float g = gamma2[tid];
        s2[tid] = g * r;
        t2[tid] = beta2[tid] - g * mean * r;
    }
    __syncthreads();
    const int c = tid & 63, rl = tid >> 6;
    for (int row = blockIdx.x * 4 + rl; row < Nn; row += gridDim.x * 4) {
        size_t idx = (size_t)row * ELEMF + c;
        float v = fmaf(s2[c], g_sums[idx], t2[c]) + atom[idx];
        outp[idx] = softplusf(v);
    }
}

extern "C" void kernel_launch(void* const* d_in, const int* in_sizes, int n_in,
                              void* d_out, int out_size)
{
    const float* atom   = (const float*)d_in[0];
    const float* nbrfea = (const float*)d_in[1];
    const int*   sIdx   = (const int*)d_in[2];
    const int*   nIdx   = (const int*)d_in[3];
    const float* W      = (const float*)d_in[4];
    const float* b      = (const float*)d_in[5];
    const float* gamma1 = (const float*)d_in[6];
    const float* beta1  = (const float*)d_in[7];
    const float* gamma2 = (const float*)d_in[8];
    const float* beta2  = (const float*)d_in[9];
    float* outp = (float*)d_out;

    const int Nn = in_sizes[0] / ELEMF;
    const int E  = in_sizes[2];

    zero_kernel<<<2048, 256>>>(Nn * ELEMF);

    int gemm_blocks = (E + 63) / 64;
    gemm_stats_kernel<<<gemm_blocks, 256>>>(atom, nbrfea, sIdx, nIdx, W, b, E);

    int lanes = (E + 63) / 64;
    int msg_blocks = (lanes + 3) / 4;
    msg_segsum_kernel<<<msg_blocks, 256>>>(sIdx, gamma1, beta1, E, 1.f / (float)E);

    stats2_kernel<<<592, 256>>>(Nn);

    int out_blocks = (Nn + 3) / 4;
    out_kernel<<<out_blocks, 256>>>(atom, gamma2, beta2, outp, Nn, 1.f / (float)Nn);
}

// round 3
// speedup vs baseline: 1.8533x; 1.8533x over previous
#include <cuda_runtime.h>
#include <cuda_bf16.h>

#define ELEMF 64
#define NBRF  32
#define COUT  128
#define KTOT  160
#define EPS   1e-5f
#define E_MAX 1600000
#define N_MAX 50000

// row stride for bf16 smem tiles: 168 bf16 = 336 bytes (84 banks = 20 mod 32 -> conflict-free LDSM)
#define RSTRIDE_E 168
#define RSTRIDE_B 336
#define TILE_BYTES (128 * RSTRIDE_B)   // 43008

// ---------------- scratch (device globals; no allocation allowed) -----------
__device__ float g_hidden[(size_t)E_MAX * COUT];   // pre-BN1 hidden (E,128)
__device__ float g_sums[(size_t)N_MAX * ELEMF];    // segment sums (N,64)
__device__ float g_stats1[2 * COUT];               // sum / sumsq per hidden col
__device__ float g_stats2[2 * ELEMF];              // sum / sumsq per summed col
// Pre-split W: 2 bufs (hi, lo), each [128 n][160 k (stride 168)] bf16
__device__ unsigned char g_Bsw[2 * TILE_BYTES];

// ---------------- helpers -----------------------------------------------------
__device__ __forceinline__ unsigned smem_u32(const void* p) {
    unsigned a;
    asm("{ .reg .u64 t; cvta.to.shared.u64 t, %1; cvt.u32.u64 %0, t; }"
        : "=r"(a) : "l"(p));
    return a;
}
__device__ __forceinline__ unsigned bf2(float a, float b) {  // elem0=a, elem1=b
    unsigned r;
    asm("cvt.rn.bf16x2.f32 %0, %1, %2;" : "=r"(r) : "f"(b), "f"(a));
    return r;
}
__device__ __forceinline__ void ldsm4(unsigned addr, unsigned& r0, unsigned& r1,
                                      unsigned& r2, unsigned& r3) {
    asm volatile("ldmatrix.sync.aligned.m8n8.x4.shared.b16 {%0,%1,%2,%3}, [%4];"
                 : "=r"(r0), "=r"(r1), "=r"(r2), "=r"(r3) : "r"(addr));
}
__device__ __forceinline__ void mma16816(float* d, const unsigned* a,
                                         unsigned b0, unsigned b1) {
    asm volatile("mma.sync.aligned.m16n8k16.row.col.f32.bf16.bf16.f32 "
                 "{%0,%1,%2,%3}, {%4,%5,%6,%7}, {%8,%9}, {%0,%1,%2,%3};"
                 : "+f"(d[0]), "+f"(d[1]), "+f"(d[2]), "+f"(d[3])
                 : "r"(a[0]), "r"(a[1]), "r"(a[2]), "r"(a[3]), "r"(b0), "r"(b1));
}
// split 8 fp32 -> hi/lo bf16x2 quads
__device__ __forceinline__ void split8(float4 v0, float4 v1, uint4& hi, uint4& lo) {
    hi.x = bf2(v0.x, v0.y); hi.y = bf2(v0.z, v0.w);
    hi.z = bf2(v1.x, v1.y); hi.w = bf2(v1.z, v1.w);
    float l0 = v0.x - __uint_as_float(hi.x << 16);
    float l1 = v0.y - __uint_as_float(hi.x & 0xFFFF0000u);
    float l2 = v0.z - __uint_as_float(hi.y << 16);
    float l3 = v0.w - __uint_as_float(hi.y & 0xFFFF0000u);
    float l4 = v1.x - __uint_as_float(hi.z << 16);
    float l5 = v1.y - __uint_as_float(hi.z & 0xFFFF0000u);
    float l6 = v1.z - __uint_as_float(hi.w << 16);
    float l7 = v1.w - __uint_as_float(hi.w & 0xFFFF0000u);
    lo.x = bf2(l0, l1); lo.y = bf2(l2, l3);
    lo.z = bf2(l4, l5); lo.w = bf2(l6, l7);
}

// ---------------- kernels ----------------------------------------------------
__global__ void zero_kernel(int n_sums) {
    int i = blockIdx.x * blockDim.x + threadIdx.x;
    int stride = gridDim.x * blockDim.x;
    for (int j = i; j < n_sums; j += stride) g_sums[j] = 0.f;
    if (i < 2 * COUT)  g_stats1[i] = 0.f;
    if (i < 2 * ELEMF) g_stats2[i] = 0.f;
}

// Split W (160x128 fp32, row-major [k][n]) into hi/lo bf16 [n][k] tiles.
__global__ void wsplit_kernel(const float* __restrict__ W) {
    int i = blockIdx.x * blockDim.x + threadIdx.x;   // 2*128*160 = 40960
    if (i >= 2 * 128 * KTOT) return;
    int k   = i % KTOT;
    int n   = (i / KTOT) & 127;
    int buf = i / (128 * KTOT);
    float w = W[k * COUT + n];
    __nv_bfloat16 h = __float2bfloat16_rn(w);
    unsigned short out;
    if (buf == 0) {
        out = *reinterpret_cast<unsigned short*>(&h);
    } else {
        float lo = w - __bfloat162float(h);
        __nv_bfloat16 l = __float2bfloat16_rn(lo);
        out = *reinterpret_cast<unsigned short*>(&l);
    }
    *reinterpret_cast<unsigned short*>(g_Bsw + buf * TILE_BYTES + n * RSTRIDE_B + k * 2) = out;
}

// Persistent HMMA gather-GEMM. Tile = 128 edges x 128 outputs.
// A = concat(atom[self], atom[nbr], nbr_fea) split hi/lo bf16.
// hidden = Ah@Bh + Al@Bh + Ah@Bl + bias. BN1 col stats accumulated via shuffles.
__global__ __launch_bounds__(256, 1) void gemm_tc_kernel(
    const float* __restrict__ atom, const float* __restrict__ nbrfea,
    const int* __restrict__ selfIdx, const int* __restrict__ nbrIdx,
    const float* __restrict__ bias, int E, int nTiles)
{
    extern __shared__ char smem[];
    const unsigned sbase = smem_u32(smem);

    const int AH_OFF  = 0;
    const int AL_OFF  = TILE_BYTES;
    const int BH_OFF  = 2 * TILE_BYTES;
    const int BL_OFF  = 3 * TILE_BYTES;
    const int BIAS_OFF = 4 * TILE_BYTES;          // 512 B
    const int STAT_OFF = BIAS_OFF + 512;          // 1024 B

    const int tid = threadIdx.x, wid = tid >> 5, lane = tid & 31;

    // B tiles (pre-split image) -> smem, once per CTA
    {
        const uint4* src = reinterpret_cast<const uint4*>(g_Bsw);
        uint4* dst = reinterpret_cast<uint4*>(smem + BH_OFF);
        for (int i = tid; i < 2 * TILE_BYTES / 16; i += 256) dst[i] = src[i];
    }
    if (tid < COUT) reinterpret_cast<float*>(smem + BIAS_OFF)[tid] = bias[tid];
    reinterpret_cast<float*>(smem + STAT_OFF)[tid] = 0.f;   // 256 stats slots
    __syncthreads();

    // warp tiling: 2 m-warps x 4 n-warps; warp tile = m64 x n32
    const int wm = (wid >> 2) * 64;
    const int wn = (wid & 3) * 32;
    const unsigned lane_off = (lane & 15) * RSTRIDE_B + ((lane >> 4) << 4);

    // per-thread fixed output columns: cb + 8j, cb = wn + 2*(lane&3)
    const int cb = wn + 2 * (lane & 3);
    float bc0[4], bc1[4];
#pragma unroll
    for (int j = 0; j < 4; ++j) {
        bc0[j] = reinterpret_cast<float*>(smem + BIAS_OFF)[cb + 8 * j];
        bc1[j] = reinterpret_cast<float*>(smem + BIAS_OFF)[cb + 8 * j + 1];
    }

    const unsigned aoff[3] = {sbase + AH_OFF, sbase + AL_OFF, sbase + AH_OFF};
    const unsigned boff[3] = {sbase + BH_OFF, sbase + BH_OFF, sbase + BL_OFF};
    float* sstat = reinterpret_cast<float*>(smem + STAT_OFF);

    for (int tile = blockIdx.x; tile < nTiles; tile += gridDim.x) {
        const int eb = tile * 128;
        __syncthreads();   // previous iteration's LDSM must be done before overwrite

        // ----- gather + split A: thread pair per row -----
        {
            const int r = tid >> 1, h = tid & 1;
            const int e = eb + r;
            const bool v = (e < E);
            const int si = v ? selfIdx[e] : 0;
            const int ni = v ? nbrIdx[e] : 0;
            const float4 Z = make_float4(0.f, 0.f, 0.f, 0.f);
            char* rowH = smem + AH_OFF + r * RSTRIDE_B;
            char* rowL = smem + AL_OFF + r * RSTRIDE_B;
            // seg 0/1: atom features (each thread does 32 cols of each)
#pragma unroll
            for (int seg = 0; seg < 2; ++seg) {
                const float* src = atom + (size_t)(seg == 0 ? si : ni) * ELEMF + h * 32;
                const int kb = seg * 128 + h * 64;   // byte offset of k base
#pragma unroll
                for (int g = 0; g < 4; ++g) {
                    float4 v0 = v ? reinterpret_cast<const float4*>(src)[g * 2]     : Z;
                    float4 v1 = v ? reinterpret_cast<const float4*>(src)[g * 2 + 1] : Z;
                    uint4 hi, lo;
                    split8(v0, v1, hi, lo);
                    *reinterpret_cast<uint4*>(rowH + kb + g * 16) = hi;
                    *reinterpret_cast<uint4*>(rowL + kb + g * 16) = lo;
                }
            }
            // seg 2: edge features, 16 cols per thread
            {
                const float* src = nbrfea + (size_t)e * NBRF + h * 16;
                const int kb = 256 + h * 32;
#pragma unroll
                for (int g = 0; g < 2; ++g) {
                    float4 v0 = v ? reinterpret_cast<const float4*>(src)[g * 2]     : Z;
                    float4 v1 = v ? reinterpret_cast<const float4*>(src)[g * 2 + 1] : Z;
                    uint4 hi, lo;
                    split8(v0, v1, hi, lo);
                    *reinterpret_cast<uint4*>(rowH + kb + g * 16) = hi;
                    *reinterpret_cast<uint4*>(rowL + kb + g * 16) = lo;
                }
            }
        }
        __syncthreads();

        // ----- HMMA: 3 passes (Ah,Bh)(Al,Bh)(Ah,Bl), K=160 each -----
        float d[4][4][4];
#pragma unroll
        for (int i = 0; i < 4; ++i)
#pragma unroll
            for (int j = 0; j < 4; ++j)
#pragma unroll
                for (int q = 0; q < 4; ++q) d[i][j][q] = 0.f;

#pragma unroll
        for (int p = 0; p < 3; ++p) {
            const unsigned abase = aoff[p] + wm * RSTRIDE_B + lane_off;
            const unsigned bbase = boff[p] + wn * RSTRIDE_B + lane_off;
#pragma unroll
            for (int kk = 0; kk < 10; ++kk) {
                const unsigned kb = kk * 32;
                unsigned a[4][4];
#pragma unroll
                for (int i = 0; i < 4; ++i)
                    ldsm4(abase + i * 16 * RSTRIDE_B + kb,
                          a[i][0], a[i][1], a[i][2], a[i][3]);
                unsigned u0, u1, u2, u3, w0, w1, w2, w3;
                ldsm4(bbase + kb, u0, u1, u2, u3);                      // n frags 0,1
                ldsm4(bbase + 16 * RSTRIDE_B + kb, w0, w1, w2, w3);     // n frags 2,3
#pragma unroll
                for (int i = 0; i < 4; ++i) {
                    mma16816(d[i][0], a[i], u0, u2);
                    mma16816(d[i][1], a[i], u1, u3);
                    mma16816(d[i][2], a[i], w0, w2);
                    mma16816(d[i][3], a[i], w1, w3);
                }
            }
        }

        // ----- epilogue: bias, store hidden, BN1 stats -----
#pragma unroll
        for (int i = 0; i < 4; ++i) {
            const int e1 = eb + wm + 16 * i + (lane >> 2);
            const int e2 = e1 + 8;
            const bool v1 = (e1 < E), v2 = (e2 < E);
            float* out1 = g_hidden + (size_t)e1 * COUT + cb;
            float* out2 = g_hidden + (size_t)e2 * COUT + cb;
#pragma unroll
            for (int j = 0; j < 4; ++j) {
                float v00 = d[i][j][0] + bc0[j];
                float v01 = d[i][j][1] + bc1[j];
                float v10 = d[i][j][2] + bc0[j];
                float v11 = d[i][j][3] + bc1[j];
                if (v1) *reinterpret_cast<float2*>(out1 + 8 * j) = make_float2(v00, v01);
                if (v2) *reinterpret_cast<float2*>(out2 + 8 * j) = make_float2(v10, v11);
                float s0 = (v1 ? v00 : 0.f) + (v2 ? v10 : 0.f);
                float s1 = (v1 ? v01 : 0.f) + (v2 ? v11 : 0.f);
                float q0 = (v1 ? v00 * v00 : 0.f) + (v2 ? v10 * v10 : 0.f);
                float q1 = (v1 ? v01 * v01 : 0.f) + (v2 ? v11 * v11 : 0.f);
                // stash back into d for the cross-i reduction below
                d[i][j][0] = s0; d[i][j][1] = s1; d[i][j][2] = q0; d[i][j][3] = q1;
            }
        }
        // sum over i in-register, then reduce over the 8 row-groups per warp
#pragma unroll
        for (int j = 0; j < 4; ++j) {
            float s0 = d[0][j][0] + d[1][j][0] + d[2][j][0] + d[3][j][0];
            float s1 = d[0][j][1] + d[1][j][1] + d[2][j][1] + d[3][j][1];
            float q0 = d[0][j][2] + d[1][j][2] + d[2][j][2] + d[3][j][2];
            float q1 = d[0][j][3] + d[1][j][3] + d[2][j][3] + d[3][j][3];
#pragma unroll
            for (int ofs = 4; ofs <= 16; ofs <<= 1) {
                s0 += __shfl_xor_sync(0xFFFFFFFF, s0, ofs);
                s1 += __shfl_xor_sync(0xFFFFFFFF, s1, ofs);
                q0 += __shfl_xor_sync(0xFFFFFFFF, q0, ofs);
                q1 += __shfl_xor_sync(0xFFFFFFFF, q1, ofs);
            }
            if (lane < 4) {
                const int c = wn + 2 * lane + 8 * j;
                atomicAdd(&sstat[c], s0);
                atomicAdd(&sstat[c + 1], s1);
                atomicAdd(&sstat[COUT + c], q0);
                atomicAdd(&sstat[COUT + c + 1], q1);
            }
        }
    }

    __syncthreads();
    atomicAdd(&g_stats1[tid], sstat[tid]);   // tid covers all 256 slots
}

__device__ __forceinline__ float softplusf(float x) {
    return (x > 15.f) ? x : log1pf(expf(x));
}

// Apply BN1, sigmoid(filter)*softplus(core), segment-sum over sorted self idx.
__global__ __launch_bounds__(256) void msg_segsum_kernel(
    const int* __restrict__ selfIdx,
    const float* __restrict__ gamma1, const float* __restrict__ beta1,
    int E, float invE)
{
    __shared__ float s1[128], t1[128];
    const int tid = threadIdx.x;
    if (tid < 128) {
        float mean = g_stats1[tid] * invE;
        float var  = g_stats1[128 + tid] * invE - mean * mean;
        float r = rsqrtf(var + EPS);
        float g = gamma1[tid];
        s1[tid] = g * r;
        t1[tid] = beta1[tid] - g * mean * r;
    }
    __syncthreads();

    const int c = tid & 63;
    const int lane = tid >> 6;
    const int CHUNK = 64;
    long gl = (long)blockIdx.x * 4 + lane;
    int es = (int)(gl * CHUNK);
    if (es >= E) return;
    int ee = min(es + CHUNK, E);

    const float sf = s1[c],      tf = t1[c];
    const float sc = s1[64 + c], tc = t1[64 + c];

    int cur = selfIdx[es];
    float accv = 0.f;
    for (int e = es; e < ee; ++e) {
        int a = selfIdx[e];
        if (a != cur) {
            atomicAdd(&g_sums[(size_t)cur * ELEMF + c], accv);
            cur = a; accv = 0.f;
        }
        float f = fmaf(sf, g_hidden[(size_t)e * COUT + c], tf);
        float g = fmaf(sc, g_hidden[(size_t)e * COUT + 64 + c], tc);
        float sig = 1.f / (1.f + expf(-f));
        accv = fmaf(sig, softplusf(g), accv);
    }
    atomicAdd(&g_sums[(size_t)cur * ELEMF + c], accv);
}

__global__ __launch_bounds__(256) void stats2_kernel(int Nn) {
    __shared__ float rs[4][64];
    __shared__ float rq[4][64];
    const int tid = threadIdx.x;
    const int c = tid & 63, rl = tid >> 6;
    float s = 0.f, q = 0.f;
    for (int row = blockIdx.x * 4 + rl; row < Nn; row += gridDim.x * 4) {
        float v = g_sums[(size_t)row * ELEMF + c];
        s += v; q += v * v;
    }
    rs[rl][c] = s; rq[rl][c] = q;
    __syncthreads();
    if (tid < 64) {
        float ss = 0.f, qq = 0.f;
#pragma unroll
        for (int r = 0; r < 4; ++r) { ss += rs[r][tid]; qq += rq[r][tid]; }
        atomicAdd(&g_stats2[tid], ss);
        atomicAdd(&g_stats2[64 + tid], qq);
    }
}

__global__ __launch_bounds__(256) void out_kernel(
    const float* __restrict__ atom,
    const float* __restrict__ gamma2, const float* __restrict__ beta2,
    float* __restrict__ outp, int Nn, float invN)
{
    __shared__ float s2[64], t2[64];
    const int tid = threadIdx.x;
    if (tid < 64) {
        float mean = g_stats2[tid] * invN;
        float var  = g_stats2[64 + tid] * invN - mean * mean;
        float r = rsqrtf(var + EPS);
        float g = gamma2[tid];
        s2[tid] = g * r;
        t2[tid] = beta2[tid] - g * mean * r;
    }
    __syncthreads();
    const int c = tid & 63, rl = tid >> 6;
    for (int row = blockIdx.x * 4 + rl; row < Nn; row += gridDim.x * 4) {
        size_t idx = (size_t)row * ELEMF + c;
        float v = fmaf(s2[c], g_sums[idx], t2[c]) + atom[idx];
        outp[idx] = softplusf(v);
    }
}

extern "C" void kernel_launch(void* const* d_in, const int* in_sizes, int n_in,
                              void* d_out, int out_size)
{
    const float* atom   = (const float*)d_in[0];
    const float* nbrfea = (const float*)d_in[1];
    const int*   sIdx   = (const int*)d_in[2];
    const int*   nIdx   = (const int*)d_in[3];
    const float* W      = (const float*)d_in[4];
    const float* b      = (const float*)d_in[5];
    const float* gamma1 = (const float*)d_in[6];
    const float* beta1  = (const float*)d_in[7];
    const float* gamma2 = (const float*)d_in[8];
    const float* beta2  = (const float*)d_in[9];
    float* outp = (float*)d_out;

    const int Nn = in_sizes[0] / ELEMF;
    const int E  = in_sizes[2];
    const int nTiles = (E + 127) / 128;

    const int SMEM_BYTES = 4 * TILE_BYTES + 512 + 1024;   // 173568
    cudaFuncSetAttribute(gemm_tc_kernel,
                         cudaFuncAttributeMaxDynamicSharedMemorySize, SMEM_BYTES);
    int sms = 148;
    cudaDeviceGetAttribute(&sms, cudaDevAttrMultiProcessorCount, 0);
    int grid = sms < nTiles ? sms : nTiles;

    zero_kernel<<<2048, 256>>>(Nn * ELEMF);
    wsplit_kernel<<<(2 * 128 * KTOT + 255) / 256, 256>>>(W);
    gemm_tc_kernel<<<grid, 256, SMEM_BYTES>>>(atom, nbrfea, sIdx, nIdx, b, E, nTiles);

    int lanes = (E + 63) / 64;
    int msg_blocks = (lanes + 3) / 4;
    msg_segsum_kernel<<<msg_blocks, 256>>>(sIdx, gamma1, beta1, E, 1.f / (float)E);

    stats2_kernel<<<592, 256>>>(Nn);

    int out_blocks = (Nn + 3) / 4;
    out_kernel<<<out_blocks, 256>>>(atom, gamma2, beta2, outp, Nn, 1.f / (float)Nn);
}